// round 15
// baseline (speedup 1.0000x reference)
#include <cuda_runtime.h>
#include <cuda_bf16.h>
#include <math.h>

#define N_NODES   3000
#define HID       64
#define MAXD      128
#define NGRP      4
#define BATCH     256
#define SEQL      50
#define RPB       11                 // rows per block
#define NWARPS    (RPB * 2)          // 2 warps per row
#define NTHREADS  (NWARPS * 32)      // 704
#define GRID2     296                // 2 blocks per SM x 148 SMs
#define NSLOTS    4

// dynamic smem layout: [sedge RPB*128*8][sW 49152][sh RPB*65*4]
#define SM_EDGE_BYTES (RPB * MAXD * 8)
#define SM_W_BYTES    (3 * HID * HID * 4)
#define SM_H_BYTES    (RPB * (HID + 1) * 4)
#define MAGNA_SMEM    (SM_EDGE_BYTES + SM_W_BYTES + SM_H_BYTES)

// ---------------- scratch (device globals; no allocation) ----------------
__device__ int   g_col[N_NODES * MAXD];
__device__ int   g_deg[N_NODES];
__device__ int   g_degp[N_NODES];
__device__ __align__(16) float g_q  [N_NODES * HID];
__device__ __align__(16) float g_k  [N_NODES * HID];
__device__ __align__(16) float g_v  [N_NODES * HID];
__device__ __align__(16) float g_q2 [N_NODES * HID];
__device__ __align__(16) float g_k2 [N_NODES * HID];
__device__ __align__(16) float g_v2 [N_NODES * HID];
__device__ __align__(16) float g_zA [N_NODES * HID];
__device__ __align__(16) float g_zB [N_NODES * HID];
__device__ __align__(16) float g_zC [N_NODES * HID];
__device__ __align__(16) float g_zD [N_NODES * HID];
__device__ __align__(16) float g_zE [N_NODES * HID];
__device__ __align__(16) float g_zF [N_NODES * HID];
__device__ __align__(16) float g_h  [N_NODES * HID];
__device__ float g_ss2[N_NODES];
__device__ float g_P  [NGRP * HID + 1];
__device__ unsigned g_ver[N_NODES];       // per-node phase version (dataflow flags)
__device__ unsigned g_bar[NSLOTS];

// ---------------- grid barrier (nanosleep flavor; used ONCE pre-finalize) ----------------
__device__ __forceinline__ void grid_barrier(int slot) {
    __syncthreads();
    if (threadIdx.x == 0) {
        __threadfence();
        atomicAdd(&g_bar[slot], 1u);
        unsigned v;
        do {
            asm volatile("ld.global.acquire.gpu.u32 %0, [%1];"
                         : "=r"(v) : "l"(&g_bar[slot]));
            if (v >= (unsigned)gridDim.x) break;
            __nanosleep(64);
        } while (true);
    }
    __syncthreads();
}

// wait until all of row i's neighbor versions reach `need` (warp-cooperative)
__device__ __forceinline__ void wait_edges(int i, int degp, int lane, unsigned need) {
    const int* __restrict__ cp = &g_col[i * MAXD];
    for (int e = lane; e < degp; e += 32) {
        int j = __ldg(&cp[e]);
        unsigned v;
        while (true) {
            asm volatile("ld.global.acquire.gpu.u32 %0, [%1];"
                         : "=r"(v) : "l"(g_ver + j));
            if (v >= need) break;
            __nanosleep(40);
        }
    }
    __syncwarp();
}

__device__ __forceinline__ void publish_ver(int i, unsigned val) {
    __threadfence();
    asm volatile("st.global.release.gpu.u32 [%0], %1;"
                 :: "l"(g_ver + i), "r"(val) : "memory");
}

// ---------------- 1. build CSR from dense adj (+ zero flags/accumulators) ----------------
__global__ void build_csr(const float* __restrict__ adj) {
    int i = blockIdx.x;
    if (i == 0) {
        for (int t = threadIdx.x; t <= NGRP * HID; t += blockDim.x) g_P[t] = 0.f;
        if (threadIdx.x < NSLOTS) g_bar[threadIdx.x] = 0u;
    }
    if (threadIdx.x == 0) g_ver[i] = 0u;
    __shared__ int cnt;
    if (threadIdx.x == 0) cnt = 0;
    __syncthreads();
    const float4* row = reinterpret_cast<const float4*>(adj + (size_t)i * N_NODES);
    for (int j4 = threadIdx.x; j4 < N_NODES / 4; j4 += blockDim.x) {
        float4 f = row[j4];
        int j = j4 * 4;
        if (f.x > 0.f) { int p = atomicAdd(&cnt, 1); if (p < MAXD) g_col[i * MAXD + p] = j; }
        if (f.y > 0.f) { int p = atomicAdd(&cnt, 1); if (p < MAXD) g_col[i * MAXD + p] = j + 1; }
        if (f.z > 0.f) { int p = atomicAdd(&cnt, 1); if (p < MAXD) g_col[i * MAXD + p] = j + 2; }
        if (f.w > 0.f) { int p = atomicAdd(&cnt, 1); if (p < MAXD) g_col[i * MAXD + p] = j + 3; }
    }
    __syncthreads();
    int deg = min(cnt, MAXD);
    int degp = min((deg + 7) & ~7, MAXD);
    if (threadIdx.x == 0) { g_deg[i] = deg; g_degp[i] = degp; }
    for (int p = deg + (int)threadIdx.x; p < degp; p += blockDim.x) g_col[i * MAXD + p] = 0;
}

// ---------------- 2. mega persistent kernel (dataflow-synchronized) ----------------
// Versions: qkv-L0=1, hops L0 write 2,3,4 (hop3 local-only); qkv-L1=5, hops L1 write 6,7,8.
__global__ __launch_bounds__(NTHREADS, 2) void mega_kernel(
    const float* __restrict__ emb,
    const float* __restrict__ Wq, const float* __restrict__ Wk, const float* __restrict__ Wv,
    const float* __restrict__ Wg, const float* __restrict__ bg,
    const float* __restrict__ Wp, const float* __restrict__ bp,
    const float* __restrict__ gamma, const float* __restrict__ beta,
    const int* __restrict__ cate, float* __restrict__ out)
{
    extern __shared__ char dyn[];
    float2 (*sedge)[MAXD] = reinterpret_cast<float2(*)[MAXD]>(dyn);
    float* sW = reinterpret_cast<float*>(dyn + SM_EDGE_BYTES);
    float* sh = reinterpret_cast<float*>(dyn + SM_EDGE_BYTES + SM_W_BYTES);
    __shared__ __align__(16) float4 spart[NWARPS][16];
    __shared__ float sWg[HID * NGRP];
    __shared__ float sbg2[NGRP];
    __shared__ float sws[RPB][NGRP];
    __shared__ float sswp[RPB];
    __shared__ float sf1[128], sf2[128];

    int tid  = threadIdx.x;
    int w    = tid >> 5;
    int lane = tid & 31;
    int r    = w >> 1;
    int p    = w & 1;
    int half = lane >> 4;
    int hl   = lane & 15;
    int h4   = hl * 4;
    int base = blockIdx.x * RPB;
    int i = base + r;
    bool active = (i < N_NODES);
    int deg = 0, degp = 0;
    if (active) { deg = g_deg[i]; degp = g_degp[i]; }

    for (int l = 0; l < 2; l++) {
        const float* Wql = Wq + l * HID * HID;
        const float* Wkl = Wk + l * HID * HID;
        const float* Wvl = Wv + l * HID * HID;
        float* gq = l ? g_q2 : g_q;
        float* gk = l ? g_k2 : g_k;
        float* gv = l ? g_v2 : g_v;
        unsigned VB = l ? 5u : 1u;

        // ---- phase A: stage weights (+ emb tile on layer 0) ----
        {
            float4* sW4 = reinterpret_cast<float4*>(sW);
            const float4* wq4 = reinterpret_cast<const float4*>(Wql);
            const float4* wk4 = reinterpret_cast<const float4*>(Wkl);
            const float4* wv4 = reinterpret_cast<const float4*>(Wvl);
            for (int idx = tid; idx < HID * HID / 4; idx += NTHREADS) {
                sW4[idx]        = __ldg(&wq4[idx]);
                sW4[1024 + idx] = __ldg(&wk4[idx]);
                sW4[2048 + idx] = __ldg(&wv4[idx]);
            }
            if (l == 0) {
                for (int idx = tid; idx < RPB * HID; idx += NTHREADS) {
                    int rr = idx >> 6, c = idx & 63;
                    int gi = base + rr;
                    sh[rr * (HID + 1) + c] = (gi < N_NODES) ? __ldg(&emb[gi * HID + c]) : 0.f;
                }
            }
        }
        __syncthreads();

        // ---- phase B: QKV (528 threads: mat x row x quad, one float4 acc each) ----
        if (tid < 3 * RPB * 16) {
            int m  = tid / (RPB * 16);
            int rm = tid - m * (RPB * 16);
            int r2 = rm >> 4;
            int quad = rm & 15;
            const float4* wb = reinterpret_cast<const float4*>(sW) + m * 1024 + quad;
            const float* hrow = &sh[r2 * (HID + 1)];
            float4 a = make_float4(0.f, 0.f, 0.f, 0.f);
#pragma unroll
            for (int c = 0; c < HID; c++) {
                float4 ww = wb[c * 16];
                float hv = hrow[c];
                a.x += hv * ww.x; a.y += hv * ww.y; a.z += hv * ww.z; a.w += hv * ww.w;
            }
            int gi = base + r2;
            if (gi < N_NODES) {
                float* dst = (m == 0) ? gq : (m == 1) ? gk : gv;
                *reinterpret_cast<float4*>(&dst[gi * HID + quad * 4]) = a;
            }
        }
        __syncthreads();
        if (tid < RPB && base + tid < N_NODES) publish_ver(base + tid, VB);

        // ---- phase C: wait neighbors' qkv, then edge dots + softmax ----
        if (active) {
            wait_edges(i, degp, lane, VB);
            float4 qv = *reinterpret_cast<const float4*>(&gq[i * HID + h4]);
            const int* __restrict__ cp = &g_col[i * MAXD];
            for (int s = p * 2; s < degp; s += 4) {
                int e = s + half;
                int j = __ldg(&cp[e]);
                float4 kv = __ldg(reinterpret_cast<const float4*>(&gk[j * HID + h4]));
                float d = qv.x * kv.x + qv.y * kv.y + qv.z * kv.z + qv.w * kv.w;
                d += __shfl_xor_sync(0xffffffffu, d, 8);
                d += __shfl_xor_sync(0xffffffffu, d, 4);
                d += __shfl_xor_sync(0xffffffffu, d, 2);
                d += __shfl_xor_sync(0xffffffffu, d, 1);
                if (hl == 0) sedge[r][e] = make_float2(__int_as_float(j * HID), d);
            }
        }
        __syncthreads();
        if (active && p == 0) {
            float vals[4];
#pragma unroll
            for (int t = 0; t < 4; t++) {
                int s = lane + 32 * t;
                vals[t] = (s < deg) ? sedge[r][s].y * 0.125f : -1e30f;
            }
            float m = fmaxf(fmaxf(vals[0], vals[1]), fmaxf(vals[2], vals[3]));
#pragma unroll
            for (int o = 16; o > 0; o >>= 1) m = fmaxf(m, __shfl_xor_sync(0xffffffffu, m, o));
            float sum = 0.f;
#pragma unroll
            for (int t = 0; t < 4; t++) {
                int s = lane + 32 * t;
                float e = (s < deg) ? __expf(vals[t] - m) : 0.f;
                vals[t] = e;
                sum += e;
            }
#pragma unroll
            for (int o = 16; o > 0; o >>= 1) sum += __shfl_xor_sync(0xffffffffu, sum, o);
            float inv = 1.f / sum;
#pragma unroll
            for (int t = 0; t < 4; t++) {
                int s = lane + 32 * t;
                if (s < degp) sedge[r][s].y = (s < deg) ? vals[t] * inv : 0.f;
            }
        }
        __syncthreads();

        // ---- phase D: 4 hops (dataflow-gated, no global barriers) ----
#pragma unroll
        for (int hop = 0; hop < 4; hop++) {
            const float* __restrict__ zin =
                (hop == 0) ? gv
              : (hop == 1) ? (l ? g_zD : g_zA)
              : (hop == 2) ? (l ? g_zE : g_zB)
              :              (l ? g_zF : g_zC);
            float* __restrict__ zout =
                (hop == 0) ? (l ? g_zD : g_zA)
              : (hop == 1) ? (l ? g_zE : g_zB)
              : (hop == 2) ? (l ? g_zF : g_zC)
              :              g_h;          // only written for l==1
            float ax = 0.f, ay = 0.f, az = 0.f, aw = 0.f;
            float4 v4 = make_float4(0.f, 0.f, 0.f, 0.f);
            if (active) {
                wait_edges(i, degp, lane, VB + (unsigned)hop);
                if (p == 0 && half == 0)
                    v4 = __ldg(reinterpret_cast<const float4*>(&gv[i * HID + h4]));
                const float4* __restrict__ s4 = reinterpret_cast<const float4*>(sedge[r]);
                for (int s = p * 8; s < degp; s += 16) {
                    int q = s >> 1;
#pragma unroll
                    for (int t = 0; t < 4; t++) {
                        float4 e2 = s4[q + t];
                        float cj = half ? e2.z : e2.x;
                        float cc = half ? e2.w : e2.y;
                        float4 z = __ldg(reinterpret_cast<const float4*>(&zin[__float_as_int(cj) + h4]));
                        ax += cc * z.x; ay += cc * z.y; az += cc * z.z; aw += cc * z.w;
                    }
                }
                ax += __shfl_down_sync(0xffffffffu, ax, 16);
                ay += __shfl_down_sync(0xffffffffu, ay, 16);
                az += __shfl_down_sync(0xffffffffu, az, 16);
                aw += __shfl_down_sync(0xffffffffu, aw, 16);
            }
            if (half == 0) spart[w][hl] = make_float4(ax, ay, az, aw);
            __syncthreads();
            if (active && p == 0) {
                if (half == 0) {
                    float4 pa = spart[w][hl];
                    float4 pb = spart[w + 1][hl];
                    float4 rr;
                    rr.x = 0.85f * (pa.x + pb.x) + 0.15f * v4.x;
                    rr.y = 0.85f * (pa.y + pb.y) + 0.15f * v4.y;
                    rr.z = 0.85f * (pa.z + pb.z) + 0.15f * v4.z;
                    rr.w = 0.85f * (pa.w + pb.w) + 0.15f * v4.w;
                    if (hop == 3) {
                        int sb = r * (HID + 1) + h4;
                        rr.x += sh[sb + 0]; rr.y += sh[sb + 1];
                        rr.z += sh[sb + 2]; rr.w += sh[sb + 3];
                        sh[sb + 0] = rr.x; sh[sb + 1] = rr.y;
                        sh[sb + 2] = rr.z; sh[sb + 3] = rr.w;
                        if (l == 1)
                            *reinterpret_cast<float4*>(&g_h[i * HID + h4]) = rr;
                    } else {
                        *reinterpret_cast<float4*>(&zout[i * HID + h4]) = rr;
                    }
                }
                __syncwarp();
                if (lane == 0 && hop < 3) publish_ver(i, VB + (unsigned)hop + 1u);
            }
            __syncthreads();   // protects spart & sh reuse
        }
    }

    // ---- cluster phase: logits + softmax + ss2 + P partials (own rows, smem h) ----
    for (int idx = tid; idx < HID * NGRP; idx += NTHREADS) sWg[idx] = Wg[idx];
    if (tid < NGRP) sbg2[tid] = bg[tid];
    __syncthreads();
    if (w < RPB && lane < 16) {
        int i2 = base + w;
        int sb = w * (HID + 1) + h4;
        float h0 = sh[sb + 0], h1 = sh[sb + 1], h2 = sh[sb + 2], h3 = sh[sb + 3];
        float lg0 = h0 * sWg[(h4+0)*4+0] + h1 * sWg[(h4+1)*4+0] + h2 * sWg[(h4+2)*4+0] + h3 * sWg[(h4+3)*4+0];
        float lg1 = h0 * sWg[(h4+0)*4+1] + h1 * sWg[(h4+1)*4+1] + h2 * sWg[(h4+2)*4+1] + h3 * sWg[(h4+3)*4+1];
        float lg2 = h0 * sWg[(h4+0)*4+2] + h1 * sWg[(h4+1)*4+2] + h2 * sWg[(h4+2)*4+2] + h3 * sWg[(h4+3)*4+2];
        float lg3 = h0 * sWg[(h4+0)*4+3] + h1 * sWg[(h4+1)*4+3] + h2 * sWg[(h4+2)*4+3] + h3 * sWg[(h4+3)*4+3];
#pragma unroll
        for (int o = 8; o > 0; o >>= 1) {
            lg0 += __shfl_xor_sync(0xffffu, lg0, o);
            lg1 += __shfl_xor_sync(0xffffu, lg1, o);
            lg2 += __shfl_xor_sync(0xffffu, lg2, o);
            lg3 += __shfl_xor_sync(0xffffu, lg3, o);
        }
        if (hl == 0) {
            if (i2 < N_NODES) {
                lg0 += sbg2[0]; lg1 += sbg2[1]; lg2 += sbg2[2]; lg3 += sbg2[3];
                float m = fmaxf(fmaxf(lg0, lg1), fmaxf(lg2, lg3));
                float e0 = __expf(lg0 - m), e1 = __expf(lg1 - m), e2 = __expf(lg2 - m), e3 = __expf(lg3 - m);
                float inv = 1.f / (e0 + e1 + e2 + e3);
                float s0 = e0 * inv, s1 = e1 * inv, s2 = e2 * inv, s3 = e3 * inv;
                g_ss2[i2] = s0 * s0 + s1 * s1 + s2 * s2 + s3 * s3;
                float wpv = __ldg(&Wp[i2]);
                sws[w][0] = s0 * wpv; sws[w][1] = s1 * wpv;
                sws[w][2] = s2 * wpv; sws[w][3] = s3 * wpv;
                sswp[w] = wpv;
            } else {
                sws[w][0] = sws[w][1] = sws[w][2] = sws[w][3] = 0.f;
                sswp[w] = 0.f;
            }
        }
    }
    __syncthreads();
    if (tid < 256) {
        int g = tid >> 6, h = tid & 63;
        float acc = 0.f;
#pragma unroll
        for (int rr = 0; rr < RPB; rr++)
            acc += sws[rr][g] * sh[rr * (HID + 1) + h];
        atomicAdd(&g_P[g * HID + h], acc);
    }
    if (tid < 32) {
        float v = (tid < RPB) ? sswp[tid] : 0.f;
#pragma unroll
        for (int o = 16; o > 0; o >>= 1) v += __shfl_xor_sync(0xffffffffu, v, o);
        if (tid == 0) atomicAdd(&g_P[NGRP * HID], v);
    }
    grid_barrier(0);   // the ONLY global barrier: P, ss2, h complete chip-wide

    // ---- finalize phase: 1 user per block, 128 threads (sequence split 2-way) ----
    int u = blockIdx.x;
    if (u < BATCH && tid < 128) {
        int grp = tid >> 6;
        int h = tid & 63;
        float S1 = 0.f, S2 = 0.f;
        for (int lq = grp; lq < SEQL; lq += 2) {
            int c = __ldg(&cate[u * SEQL + lq]);
            if (c != 0) {
                float gv2 = __ldg(&g_h[c * HID + h]);
                S1 += gv2;
                S2 += gv2 * gv2 * __ldg(&g_ss2[c]);
            }
        }
        sf1[tid] = S1;
        sf2[tid] = S2;
    }
    __syncthreads();
    if (u < BATCH && tid < 64) {
        int h = tid;
        float S1 = sf1[h] + sf1[h + 64];
        float S2 = sf2[h] + sf2[h + 64];
        const float invn = 1.f / (float)(NGRP * SEQL);
        float mean = S1 * invn;
        float var  = S2 * invn - mean * mean;
        float inv  = rsqrtf(var + 1e-5f);
        float ga = __ldg(&gamma[h]), be = __ldg(&beta[h]);
        float Swp = g_P[NGRP * HID];
        float bpv = __ldg(&bp[0]);
        float k1 = inv * ga;
        float addc = be * Swp + bpv;
        float ms = mean * Swp;
#pragma unroll
        for (int g = 0; g < NGRP; g++) {
            out[(u * NGRP + g) * HID + h] = k1 * (g_P[g * HID + h] - ms) + addc;
        }
    }
}

// ---------------- launch ----------------
extern "C" void kernel_launch(void* const* d_in, const int* in_sizes, int n_in,
                              void* d_out, int out_size)
{
    const int*   cate  = (const int*)  d_in[0];
    const float* adj   = (const float*)d_in[1];
    const float* emb   = (const float*)d_in[2];
    const float* Wq    = (const float*)d_in[3];
    const float* Wk    = (const float*)d_in[4];
    const float* Wv    = (const float*)d_in[5];
    const float* Wg    = (const float*)d_in[6];
    const float* bg    = (const float*)d_in[7];
    const float* Wp    = (const float*)d_in[8];
    const float* bp    = (const float*)d_in[9];
    const float* gamma = (const float*)d_in[10];
    const float* beta  = (const float*)d_in[11];
    float* out = (float*)d_out;

    static bool attr_set = false;
    if (!attr_set) {
        cudaFuncSetAttribute(mega_kernel,
                             cudaFuncAttributeMaxDynamicSharedMemorySize, MAGNA_SMEM);
        attr_set = true;
    }

    build_csr<<<N_NODES, 128>>>(adj);
    mega_kernel<<<GRID2, NTHREADS, MAGNA_SMEM>>>(
        emb, Wq, Wk, Wv, Wg, bg, Wp, bp, gamma, beta, cate, out);
}

// round 16
// speedup vs baseline: 1.8309x; 1.8309x over previous
#include <cuda_runtime.h>
#include <cuda_bf16.h>
#include <math.h>

#define N_NODES   3000
#define HID       64
#define MAXD      128
#define NGRP      4
#define BATCH     256
#define SEQL      50
#define RPB       11                 // rows per block
#define NWARPS    (RPB * 2)          // 2 warps per row
#define NTHREADS  (NWARPS * 32)      // 704
#define GRID2     296                // 2 blocks per SM x 148 SMs
#define NSLOTS    9
#define MAILSTRIDE 8                 // 32B between mailboxes
#define MAILTOTAL (NSLOTS * GRID2 * MAILSTRIDE)

// dynamic smem layout: [sedge RPB*128*8][sW 49152][sh RPB*65*4]
#define SM_EDGE_BYTES (RPB * MAXD * 8)
#define SM_W_BYTES    (3 * HID * HID * 4)
#define SM_H_BYTES    (RPB * (HID + 1) * 4)
#define MAGNA_SMEM    (SM_EDGE_BYTES + SM_W_BYTES + SM_H_BYTES)

// ---------------- scratch (device globals; no allocation) ----------------
__device__ int   g_col[N_NODES * MAXD];
__device__ int   g_deg[N_NODES];
__device__ int   g_degp[N_NODES];
__device__ __align__(16) float g_q  [N_NODES * HID];
__device__ __align__(16) float g_k  [N_NODES * HID];
__device__ __align__(16) float g_v  [N_NODES * HID];
__device__ __align__(16) float g_q2 [N_NODES * HID];
__device__ __align__(16) float g_k2 [N_NODES * HID];
__device__ __align__(16) float g_v2 [N_NODES * HID];
__device__ __align__(16) float g_z0 [N_NODES * HID];
__device__ __align__(16) float g_z1 [N_NODES * HID];
__device__ __align__(16) float g_z2 [N_NODES * HID];
__device__ __align__(16) float g_h  [N_NODES * HID];
__device__ float g_ss2[N_NODES];
__device__ float g_P  [NGRP * HID + 1];
__device__ unsigned g_cnt[NSLOTS];
__device__ unsigned g_mail[MAILTOTAL];

// ---------------- mailbox grid barrier (all blocks co-resident -> deadlock-free) ----------------
__device__ __forceinline__ void grid_barrier(int slot) {
    __shared__ unsigned s_last;
    __syncthreads();
    if (threadIdx.x == 0) {
        __threadfence();                                   // release our block's writes
        unsigned old = atomicAdd(&g_cnt[slot], 1u);
        s_last = (old == (unsigned)GRID2 - 1u) ? 1u : 0u;
        if (s_last) __threadfence();                       // acquire all blocks' writes
    }
    __syncthreads();
    if (s_last) {
        // broadcast release to every block's private mailbox
        for (int b = threadIdx.x; b < GRID2; b += NTHREADS)
            asm volatile("st.global.release.gpu.u32 [%0], %1;"
                         :: "l"(g_mail + (slot * GRID2 + b) * MAILSTRIDE), "r"(1u)
                         : "memory");
    } else if (threadIdx.x == 0) {
        const unsigned* addr = g_mail + (slot * GRID2 + blockIdx.x) * MAILSTRIDE;
        unsigned v;
        do {
            asm volatile("ld.global.acquire.gpu.u32 %0, [%1];" : "=r"(v) : "l"(addr));
            if (v) break;
            __nanosleep(32);
        } while (true);
    }
    __syncthreads();
}

// ---------------- 1. build CSR from dense adj (+ zero barrier state) ----------------
__global__ void build_csr(const float* __restrict__ adj) {
    int i = blockIdx.x;
    if (i == 0) {
        for (int t = threadIdx.x; t <= NGRP * HID; t += blockDim.x) g_P[t] = 0.f;
        if (threadIdx.x < NSLOTS) g_cnt[threadIdx.x] = 0u;
    }
    {
        int zbase = i * 128;
        if (zbase < MAILTOTAL) {
            int t = zbase + threadIdx.x;
            if (t < MAILTOTAL) g_mail[t] = 0u;
        }
    }
    __shared__ int cnt;
    if (threadIdx.x == 0) cnt = 0;
    __syncthreads();
    const float4* row = reinterpret_cast<const float4*>(adj + (size_t)i * N_NODES);
    for (int j4 = threadIdx.x; j4 < N_NODES / 4; j4 += blockDim.x) {
        float4 f = row[j4];
        int j = j4 * 4;
        if (f.x > 0.f) { int p = atomicAdd(&cnt, 1); if (p < MAXD) g_col[i * MAXD + p] = j; }
        if (f.y > 0.f) { int p = atomicAdd(&cnt, 1); if (p < MAXD) g_col[i * MAXD + p] = j + 1; }
        if (f.z > 0.f) { int p = atomicAdd(&cnt, 1); if (p < MAXD) g_col[i * MAXD + p] = j + 2; }
        if (f.w > 0.f) { int p = atomicAdd(&cnt, 1); if (p < MAXD) g_col[i * MAXD + p] = j + 3; }
    }
    __syncthreads();
    int deg = min(cnt, MAXD);
    int degp = min((deg + 7) & ~7, MAXD);
    if (threadIdx.x == 0) { g_deg[i] = deg; g_degp[i] = degp; }
    for (int p = deg + (int)threadIdx.x; p < degp; p += blockDim.x) g_col[i * MAXD + p] = 0;
}

// ---------------- 2. mega persistent kernel ----------------
// Slots: layer0 {0:qkv, 1..3:hops}, layer1 {4:qkv, 5..7:hops}, 8:pre-finalize.
__global__ __launch_bounds__(NTHREADS, 2) void mega_kernel(
    const float* __restrict__ emb,
    const float* __restrict__ Wq, const float* __restrict__ Wk, const float* __restrict__ Wv,
    const float* __restrict__ Wg, const float* __restrict__ bg,
    const float* __restrict__ Wp, const float* __restrict__ bp,
    const float* __restrict__ gamma, const float* __restrict__ beta,
    const int* __restrict__ cate, float* __restrict__ out)
{
    extern __shared__ char dyn[];
    float2 (*sedge)[MAXD] = reinterpret_cast<float2(*)[MAXD]>(dyn);
    float* sW = reinterpret_cast<float*>(dyn + SM_EDGE_BYTES);
    float* sh = reinterpret_cast<float*>(dyn + SM_EDGE_BYTES + SM_W_BYTES);
    __shared__ __align__(16) float4 spart[NWARPS][16];
    __shared__ float sWg[HID * NGRP];
    __shared__ float sbg2[NGRP];
    __shared__ float sws[RPB][NGRP];
    __shared__ float sswp[RPB];
    __shared__ float sf1[128], sf2[128];

    int tid  = threadIdx.x;
    int w    = tid >> 5;
    int lane = tid & 31;
    int r    = w >> 1;
    int p    = w & 1;
    int half = lane >> 4;
    int hl   = lane & 15;
    int h4   = hl * 4;
    int base = blockIdx.x * RPB;
    int i = base + r;
    bool active = (i < N_NODES);
    int deg = 0, degp = 0;
    if (active) { deg = g_deg[i]; degp = g_degp[i]; }

    for (int l = 0; l < 2; l++) {
        const float* Wql = Wq + l * HID * HID;
        const float* Wkl = Wk + l * HID * HID;
        const float* Wvl = Wv + l * HID * HID;
        float* gq = l ? g_q2 : g_q;
        float* gk = l ? g_k2 : g_k;
        float* gv = l ? g_v2 : g_v;
        int lb = l ? 4 : 0;

        // ---- phase A: stage weights (+ emb tile on layer 0) ----
        {
            float4* sW4 = reinterpret_cast<float4*>(sW);
            const float4* wq4 = reinterpret_cast<const float4*>(Wql);
            const float4* wk4 = reinterpret_cast<const float4*>(Wkl);
            const float4* wv4 = reinterpret_cast<const float4*>(Wvl);
            for (int idx = tid; idx < HID * HID / 4; idx += NTHREADS) {
                sW4[idx]        = __ldg(&wq4[idx]);
                sW4[1024 + idx] = __ldg(&wk4[idx]);
                sW4[2048 + idx] = __ldg(&wv4[idx]);
            }
            if (l == 0) {
                for (int idx = tid; idx < RPB * HID; idx += NTHREADS) {
                    int rr = idx >> 6, c = idx & 63;
                    int gi = base + rr;
                    sh[rr * (HID + 1) + c] = (gi < N_NODES) ? __ldg(&emb[gi * HID + c]) : 0.f;
                }
            }
        }
        __syncthreads();

        // ---- phase B: QKV (528 threads: mat x row x quad, one float4 acc each) ----
        if (tid < 3 * RPB * 16) {
            int m  = tid / (RPB * 16);
            int rm = tid - m * (RPB * 16);
            int r2 = rm >> 4;
            int quad = rm & 15;
            const float4* wb = reinterpret_cast<const float4*>(sW) + m * 1024 + quad;
            const float* hrow = &sh[r2 * (HID + 1)];
            float4 a = make_float4(0.f, 0.f, 0.f, 0.f);
#pragma unroll
            for (int c = 0; c < HID; c++) {
                float4 ww = wb[c * 16];
                float hv = hrow[c];
                a.x += hv * ww.x; a.y += hv * ww.y; a.z += hv * ww.z; a.w += hv * ww.w;
            }
            int gi = base + r2;
            if (gi < N_NODES) {
                float* dst = (m == 0) ? gq : (m == 1) ? gk : gv;
                *reinterpret_cast<float4*>(&dst[gi * HID + quad * 4]) = a;
            }
        }
        grid_barrier(lb);              // all q/k/v visible chip-wide

        // ---- phase C: edge dots (warp pair splits edges) + softmax (even warp) ----
        if (active) {
            float4 qv = *reinterpret_cast<const float4*>(&gq[i * HID + h4]);
            const int* __restrict__ cp = &g_col[i * MAXD];
            for (int s = p * 2; s < degp; s += 4) {
                int e = s + half;
                int j = __ldg(&cp[e]);
                float4 kv = __ldg(reinterpret_cast<const float4*>(&gk[j * HID + h4]));
                float d = qv.x * kv.x + qv.y * kv.y + qv.z * kv.z + qv.w * kv.w;
                d += __shfl_xor_sync(0xffffffffu, d, 8);
                d += __shfl_xor_sync(0xffffffffu, d, 4);
                d += __shfl_xor_sync(0xffffffffu, d, 2);
                d += __shfl_xor_sync(0xffffffffu, d, 1);
                if (hl == 0) sedge[r][e] = make_float2(__int_as_float(j * HID), d);
            }
        }
        __syncthreads();
        if (active && p == 0) {
            float vals[4];
#pragma unroll
            for (int t = 0; t < 4; t++) {
                int s = lane + 32 * t;
                vals[t] = (s < deg) ? sedge[r][s].y * 0.125f : -1e30f;
            }
            float m = fmaxf(fmaxf(vals[0], vals[1]), fmaxf(vals[2], vals[3]));
#pragma unroll
            for (int o = 16; o > 0; o >>= 1) m = fmaxf(m, __shfl_xor_sync(0xffffffffu, m, o));
            float sum = 0.f;
#pragma unroll
            for (int t = 0; t < 4; t++) {
                int s = lane + 32 * t;
                float e = (s < deg) ? __expf(vals[t] - m) : 0.f;
                vals[t] = e;
                sum += e;
            }
#pragma unroll
            for (int o = 16; o > 0; o >>= 1) sum += __shfl_xor_sync(0xffffffffu, sum, o);
            float inv = 1.f / sum;
#pragma unroll
            for (int t = 0; t < 4; t++) {
                int s = lane + 32 * t;
                if (s < degp) sedge[r][s].y = (s < deg) ? vals[t] * inv : 0.f;
            }
        }
        __syncthreads();

        // ---- phase D: 4 hops; warp pair interleaves 8-edge batches ----
#pragma unroll
        for (int hop = 0; hop < 4; hop++) {
            if (hop > 0) grid_barrier(lb + hop);
            const float* __restrict__ zin =
                (hop == 0) ? gv : (hop == 1) ? g_z0 : (hop == 2) ? g_z1 : g_z2;
            float* __restrict__ zout =
                (hop == 0) ? g_z0 : (hop == 1) ? g_z1 : (hop == 2) ? g_z2 : g_h;
            float ax = 0.f, ay = 0.f, az = 0.f, aw = 0.f;
            if (active) {
                const float4* __restrict__ s4 = reinterpret_cast<const float4*>(sedge[r]);
                for (int s = p * 8; s < degp; s += 16) {
                    int q = s >> 1;
#pragma unroll
                    for (int t = 0; t < 4; t++) {
                        float4 e2 = s4[q + t];
                        float cj = half ? e2.z : e2.x;
                        float cc = half ? e2.w : e2.y;
                        float4 z = __ldg(reinterpret_cast<const float4*>(&zin[__float_as_int(cj) + h4]));
                        ax += cc * z.x; ay += cc * z.y; az += cc * z.z; aw += cc * z.w;
                    }
                }
                ax += __shfl_down_sync(0xffffffffu, ax, 16);
                ay += __shfl_down_sync(0xffffffffu, ay, 16);
                az += __shfl_down_sync(0xffffffffu, az, 16);
                aw += __shfl_down_sync(0xffffffffu, aw, 16);
            }
            if (half == 0) spart[w][hl] = make_float4(ax, ay, az, aw);
            __syncthreads();
            if (active && p == 0 && half == 0) {
                float4 pa = spart[w][hl];
                float4 pb = spart[w + 1][hl];
                float4 v4 = __ldg(reinterpret_cast<const float4*>(&gv[i * HID + h4]));
                float4 rr;
                rr.x = 0.85f * (pa.x + pb.x) + 0.15f * v4.x;
                rr.y = 0.85f * (pa.y + pb.y) + 0.15f * v4.y;
                rr.z = 0.85f * (pa.z + pb.z) + 0.15f * v4.z;
                rr.w = 0.85f * (pa.w + pb.w) + 0.15f * v4.w;
                if (hop == 3) {
                    int sb = r * (HID + 1) + h4;
                    rr.x += sh[sb + 0]; rr.y += sh[sb + 1];
                    rr.z += sh[sb + 2]; rr.w += sh[sb + 3];
                    sh[sb + 0] = rr.x; sh[sb + 1] = rr.y;
                    sh[sb + 2] = rr.z; sh[sb + 3] = rr.w;
                    if (l == 1)
                        *reinterpret_cast<float4*>(&g_h[i * HID + h4]) = rr;
                } else {
                    *reinterpret_cast<float4*>(&zout[i * HID + h4]) = rr;
                }
            }
            __syncthreads();
        }
    }

    // ---- cluster phase: logits + softmax + ss2 + P partials (own rows, smem h) ----
    for (int idx = tid; idx < HID * NGRP; idx += NTHREADS) sWg[idx] = Wg[idx];
    if (tid < NGRP) sbg2[tid] = bg[tid];
    __syncthreads();
    if (w < RPB && lane < 16) {
        int i2 = base + w;
        int sb = w * (HID + 1) + h4;
        float h0 = sh[sb + 0], h1 = sh[sb + 1], h2 = sh[sb + 2], h3 = sh[sb + 3];
        float lg0 = h0 * sWg[(h4+0)*4+0] + h1 * sWg[(h4+1)*4+0] + h2 * sWg[(h4+2)*4+0] + h3 * sWg[(h4+3)*4+0];
        float lg1 = h0 * sWg[(h4+0)*4+1] + h1 * sWg[(h4+1)*4+1] + h2 * sWg[(h4+2)*4+1] + h3 * sWg[(h4+3)*4+1];
        float lg2 = h0 * sWg[(h4+0)*4+2] + h1 * sWg[(h4+1)*4+2] + h2 * sWg[(h4+2)*4+2] + h3 * sWg[(h4+3)*4+2];
        float lg3 = h0 * sWg[(h4+0)*4+3] + h1 * sWg[(h4+1)*4+3] + h2 * sWg[(h4+2)*4+3] + h3 * sWg[(h4+3)*4+3];
#pragma unroll
        for (int o = 8; o > 0; o >>= 1) {
            lg0 += __shfl_xor_sync(0xffffu, lg0, o);
            lg1 += __shfl_xor_sync(0xffffu, lg1, o);
            lg2 += __shfl_xor_sync(0xffffu, lg2, o);
            lg3 += __shfl_xor_sync(0xffffu, lg3, o);
        }
        if (hl == 0) {
            if (i2 < N_NODES) {
                lg0 += sbg2[0]; lg1 += sbg2[1]; lg2 += sbg2[2]; lg3 += sbg2[3];
                float m = fmaxf(fmaxf(lg0, lg1), fmaxf(lg2, lg3));
                float e0 = __expf(lg0 - m), e1 = __expf(lg1 - m), e2 = __expf(lg2 - m), e3 = __expf(lg3 - m);
                float inv = 1.f / (e0 + e1 + e2 + e3);
                float s0 = e0 * inv, s1 = e1 * inv, s2 = e2 * inv, s3 = e3 * inv;
                g_ss2[i2] = s0 * s0 + s1 * s1 + s2 * s2 + s3 * s3;
                float wpv = __ldg(&Wp[i2]);
                sws[w][0] = s0 * wpv; sws[w][1] = s1 * wpv;
                sws[w][2] = s2 * wpv; sws[w][3] = s3 * wpv;
                sswp[w] = wpv;
            } else {
                sws[w][0] = sws[w][1] = sws[w][2] = sws[w][3] = 0.f;
                sswp[w] = 0.f;
            }
        }
    }
    __syncthreads();
    if (tid < 256) {
        int g = tid >> 6, h = tid & 63;
        float acc = 0.f;
#pragma unroll
        for (int rr = 0; rr < RPB; rr++)
            acc += sws[rr][g] * sh[rr * (HID + 1) + h];
        atomicAdd(&g_P[g * HID + h], acc);
    }
    if (tid < 32) {
        float v = (tid < RPB) ? sswp[tid] : 0.f;
#pragma unroll
        for (int o = 16; o > 0; o >>= 1) v += __shfl_xor_sync(0xffffffffu, v, o);
        if (tid == 0) atomicAdd(&g_P[NGRP * HID], v);
    }
    grid_barrier(8);   // P, ss2, h complete chip-wide

    // ---- finalize phase: 1 user per block, 128 threads (sequence split 2-way) ----
    int u = blockIdx.x;
    if (u < BATCH && tid < 128) {
        int grp = tid >> 6;
        int h = tid & 63;
        float S1 = 0.f, S2 = 0.f;
        for (int lq = grp; lq < SEQL; lq += 2) {
            int c = __ldg(&cate[u * SEQL + lq]);
            if (c != 0) {
                float gv2 = __ldg(&g_h[c * HID + h]);
                S1 += gv2;
                S2 += gv2 * gv2 * __ldg(&g_ss2[c]);
            }
        }
        sf1[tid] = S1;
        sf2[tid] = S2;
    }
    __syncthreads();
    if (u < BATCH && tid < 64) {
        int h = tid;
        float S1 = sf1[h] + sf1[h + 64];
        float S2 = sf2[h] + sf2[h + 64];
        const float invn = 1.f / (float)(NGRP * SEQL);
        float mean = S1 * invn;
        float var  = S2 * invn - mean * mean;
        float inv  = rsqrtf(var + 1e-5f);
        float ga = __ldg(&gamma[h]), be = __ldg(&beta[h]);
        float Swp = g_P[NGRP * HID];
        float bpv = __ldg(&bp[0]);
        float k1 = inv * ga;
        float addc = be * Swp + bpv;
        float ms = mean * Swp;
#pragma unroll
        for (int g = 0; g < NGRP; g++) {
            out[(u * NGRP + g) * HID + h] = k1 * (g_P[g * HID + h] - ms) + addc;
        }
    }
}

// ---------------- launch ----------------
extern "C" void kernel_launch(void* const* d_in, const int* in_sizes, int n_in,
                              void* d_out, int out_size)
{
    const int*   cate  = (const int*)  d_in[0];
    const float* adj   = (const float*)d_in[1];
    const float* emb   = (const float*)d_in[2];
    const float* Wq    = (const float*)d_in[3];
    const float* Wk    = (const float*)d_in[4];
    const float* Wv    = (const float*)d_in[5];
    const float* Wg    = (const float*)d_in[6];
    const float* bg    = (const float*)d_in[7];
    const float* Wp    = (const float*)d_in[8];
    const float* bp    = (const float*)d_in[9];
    const float* gamma = (const float*)d_in[10];
    const float* beta  = (const float*)d_in[11];
    float* out = (float*)d_out;

    static bool attr_set = false;
    if (!attr_set) {
        cudaFuncSetAttribute(mega_kernel,
                             cudaFuncAttributeMaxDynamicSharedMemorySize, MAGNA_SMEM);
        attr_set = true;
    }

    build_csr<<<N_NODES, 128>>>(adj);
    mega_kernel<<<GRID2, NTHREADS, MAGNA_SMEM>>>(
        emb, Wq, Wk, Wv, Wg, bg, Wp, bp, gamma, beta, cate, out);
}

// round 17
// speedup vs baseline: 2.0684x; 1.1297x over previous
#include <cuda_runtime.h>
#include <cuda_bf16.h>
#include <math.h>

#define N_NODES   3000
#define HID       64
#define MAXD      128
#define NGRP      4
#define BATCH     256
#define SEQL      50
#define RPB       11                 // rows per block
#define NWARPS    (RPB * 2)          // 2 warps per row
#define NTHREADS  (NWARPS * 32)      // 704
#define GRID2     296                // 2 blocks per SM x 148 SMs
#define NSLOTS    9

// dynamic smem layout: [sedge RPB*128*8][sW 49152][sh RPB*65*4]
#define SM_EDGE_BYTES (RPB * MAXD * 8)
#define SM_W_BYTES    (3 * HID * HID * 4)
#define SM_H_BYTES    (RPB * (HID + 1) * 4)
#define MAGNA_SMEM    (SM_EDGE_BYTES + SM_W_BYTES + SM_H_BYTES)

// ---------------- scratch (device globals; no allocation) ----------------
__device__ int   g_col[N_NODES * MAXD];
__device__ int   g_deg[N_NODES];
__device__ int   g_degp[N_NODES];
__device__ __align__(16) float g_q  [N_NODES * HID];
__device__ __align__(16) float g_k  [N_NODES * HID];
__device__ __align__(16) float g_v  [N_NODES * HID];
__device__ __align__(16) float g_q2 [N_NODES * HID];
__device__ __align__(16) float g_k2 [N_NODES * HID];
__device__ __align__(16) float g_v2 [N_NODES * HID];
__device__ __align__(16) float g_z0 [N_NODES * HID];
__device__ __align__(16) float g_z1 [N_NODES * HID];
__device__ __align__(16) float g_z2 [N_NODES * HID];
__device__ __align__(16) float g_h  [N_NODES * HID];
__device__ float g_ss2[N_NODES];
__device__ float g_P  [NGRP * HID + 1];
__device__ unsigned g_bar[NSLOTS];

// ---------------- grid barrier (round-13 flavor: atomic + nanosleep poll) ----------------
__device__ __forceinline__ void grid_barrier(int slot) {
    __syncthreads();
    if (threadIdx.x == 0) {
        __threadfence();
        atomicAdd(&g_bar[slot], 1u);
        unsigned v;
        do {
            asm volatile("ld.global.acquire.gpu.u32 %0, [%1];"
                         : "=r"(v) : "l"(&g_bar[slot]));
            if (v >= (unsigned)GRID2) break;
            __nanosleep(64);
        } while (true);
    }
    __syncthreads();
}

// ---------------- 1. build CSR from dense adj (+ zero accumulators/barriers) ----------------
__global__ void build_csr(const float* __restrict__ adj) {
    int i = blockIdx.x;
    if (i == 0) {
        for (int t = threadIdx.x; t <= NGRP * HID; t += blockDim.x) g_P[t] = 0.f;
        if (threadIdx.x < NSLOTS) g_bar[threadIdx.x] = 0u;
    }
    __shared__ int cnt;
    if (threadIdx.x == 0) cnt = 0;
    __syncthreads();
    const float4* row = reinterpret_cast<const float4*>(adj + (size_t)i * N_NODES);
    for (int j4 = threadIdx.x; j4 < N_NODES / 4; j4 += blockDim.x) {
        float4 f = row[j4];
        int j = j4 * 4;
        if (f.x > 0.f) { int p = atomicAdd(&cnt, 1); if (p < MAXD) g_col[i * MAXD + p] = j; }
        if (f.y > 0.f) { int p = atomicAdd(&cnt, 1); if (p < MAXD) g_col[i * MAXD + p] = j + 1; }
        if (f.z > 0.f) { int p = atomicAdd(&cnt, 1); if (p < MAXD) g_col[i * MAXD + p] = j + 2; }
        if (f.w > 0.f) { int p = atomicAdd(&cnt, 1); if (p < MAXD) g_col[i * MAXD + p] = j + 3; }
    }
    __syncthreads();
    int deg = min(cnt, MAXD);
    int degp = min((deg + 7) & ~7, MAXD);
    if (threadIdx.x == 0) { g_deg[i] = deg; g_degp[i] = degp; }
    for (int p = deg + (int)threadIdx.x; p < degp; p += blockDim.x) g_col[i * MAXD + p] = 0;
}

// ---------------- 2. mega persistent kernel ----------------
// Slots: layer0 {0:qkv, 1..3:hops}, layer1 {4:qkv, 5..7:hops}, 8:pre-finalize.
__global__ __launch_bounds__(NTHREADS, 2) void mega_kernel(
    const float* __restrict__ emb,
    const float* __restrict__ Wq, const float* __restrict__ Wk, const float* __restrict__ Wv,
    const float* __restrict__ Wg, const float* __restrict__ bg,
    const float* __restrict__ Wp, const float* __restrict__ bp,
    const float* __restrict__ gamma, const float* __restrict__ beta,
    const int* __restrict__ cate, float* __restrict__ out)
{
    extern __shared__ char dyn[];
    float2 (*sedge)[MAXD] = reinterpret_cast<float2(*)[MAXD]>(dyn);
    float* sW = reinterpret_cast<float*>(dyn + SM_EDGE_BYTES);
    float* sh = reinterpret_cast<float*>(dyn + SM_EDGE_BYTES + SM_W_BYTES);
    __shared__ __align__(16) float4 spart[NWARPS][16];
    __shared__ float sWg[HID * NGRP];
    __shared__ float sbg2[NGRP];
    __shared__ float sws[RPB][NGRP];
    __shared__ float sswp[RPB];
    __shared__ float sf1[128], sf2[128];

    int tid  = threadIdx.x;
    int w    = tid >> 5;
    int lane = tid & 31;
    int r    = w >> 1;
    int p    = w & 1;
    int half = lane >> 4;
    int hl   = lane & 15;
    int h4   = hl * 4;
    int base = blockIdx.x * RPB;
    int i = base + r;
    bool active = (i < N_NODES);
    int deg = 0, degp = 0;
    if (active) { deg = g_deg[i]; degp = g_degp[i]; }

    for (int l = 0; l < 2; l++) {
        const float* Wql = Wq + l * HID * HID;
        const float* Wkl = Wk + l * HID * HID;
        const float* Wvl = Wv + l * HID * HID;
        float* gq = l ? g_q2 : g_q;
        float* gk = l ? g_k2 : g_k;
        float* gv = l ? g_v2 : g_v;
        int lb = l ? 4 : 0;

        // ---- phase A: stage weights (+ emb tile on layer 0) ----
        {
            float4* sW4 = reinterpret_cast<float4*>(sW);
            const float4* wq4 = reinterpret_cast<const float4*>(Wql);
            const float4* wk4 = reinterpret_cast<const float4*>(Wkl);
            const float4* wv4 = reinterpret_cast<const float4*>(Wvl);
            for (int idx = tid; idx < HID * HID / 4; idx += NTHREADS) {
                sW4[idx]        = __ldg(&wq4[idx]);
                sW4[1024 + idx] = __ldg(&wk4[idx]);
                sW4[2048 + idx] = __ldg(&wv4[idx]);
            }
            if (l == 0) {
                for (int idx = tid; idx < RPB * HID; idx += NTHREADS) {
                    int rr = idx >> 6, c = idx & 63;
                    int gi = base + rr;
                    sh[rr * (HID + 1) + c] = (gi < N_NODES) ? __ldg(&emb[gi * HID + c]) : 0.f;
                }
            }
        }
        __syncthreads();

        // ---- phase B: QKV (528 threads: mat x row x quad, one float4 acc each) ----
        if (tid < 3 * RPB * 16) {
            int m  = tid / (RPB * 16);
            int rm = tid - m * (RPB * 16);
            int r2 = rm >> 4;
            int quad = rm & 15;
            const float4* wb = reinterpret_cast<const float4*>(sW) + m * 1024 + quad;
            const float* hrow = &sh[r2 * (HID + 1)];
            float4 a = make_float4(0.f, 0.f, 0.f, 0.f);
#pragma unroll
            for (int c = 0; c < HID; c++) {
                float4 ww = wb[c * 16];
                float hv = hrow[c];
                a.x += hv * ww.x; a.y += hv * ww.y; a.z += hv * ww.z; a.w += hv * ww.w;
            }
            int gi = base + r2;
            if (gi < N_NODES) {
                float* dst = (m == 0) ? gq : (m == 1) ? gk : gv;
                *reinterpret_cast<float4*>(&dst[gi * HID + quad * 4]) = a;
            }
        }
        grid_barrier(lb);              // all q/k/v visible chip-wide

        // ---- phase C: edge dots (warp pair splits edges) + softmax (even warp) ----
        if (active) {
            float4 qv = *reinterpret_cast<const float4*>(&gq[i * HID + h4]);
            const int* __restrict__ cp = &g_col[i * MAXD];
            for (int s = p * 2; s < degp; s += 4) {
                int e = s + half;
                int j = __ldg(&cp[e]);
                float4 kv = __ldg(reinterpret_cast<const float4*>(&gk[j * HID + h4]));
                float d = qv.x * kv.x + qv.y * kv.y + qv.z * kv.z + qv.w * kv.w;
                d += __shfl_xor_sync(0xffffffffu, d, 8);
                d += __shfl_xor_sync(0xffffffffu, d, 4);
                d += __shfl_xor_sync(0xffffffffu, d, 2);
                d += __shfl_xor_sync(0xffffffffu, d, 1);
                if (hl == 0) sedge[r][e] = make_float2(__int_as_float(j * HID), d);
            }
        }
        __syncthreads();
        if (active && p == 0) {
            float vals[4];
#pragma unroll
            for (int t = 0; t < 4; t++) {
                int s = lane + 32 * t;
                vals[t] = (s < deg) ? sedge[r][s].y * 0.125f : -1e30f;
            }
            float m = fmaxf(fmaxf(vals[0], vals[1]), fmaxf(vals[2], vals[3]));
#pragma unroll
            for (int o = 16; o > 0; o >>= 1) m = fmaxf(m, __shfl_xor_sync(0xffffffffu, m, o));
            float sum = 0.f;
#pragma unroll
            for (int t = 0; t < 4; t++) {
                int s = lane + 32 * t;
                float e = (s < deg) ? __expf(vals[t] - m) : 0.f;
                vals[t] = e;
                sum += e;
            }
#pragma unroll
            for (int o = 16; o > 0; o >>= 1) sum += __shfl_xor_sync(0xffffffffu, sum, o);
            float inv = 1.f / sum;
#pragma unroll
            for (int t = 0; t < 4; t++) {
                int s = lane + 32 * t;
                if (s < degp) sedge[r][s].y = (s < deg) ? vals[t] * inv : 0.f;
            }
        }
        __syncthreads();

        // ---- phase D: 4 hops; warp pair interleaves 8-edge batches ----
#pragma unroll
        for (int hop = 0; hop < 4; hop++) {
            if (hop > 0) grid_barrier(lb + hop);
            const float* __restrict__ zin =
                (hop == 0) ? gv : (hop == 1) ? g_z0 : (hop == 2) ? g_z1 : g_z2;
            float* __restrict__ zout =
                (hop == 0) ? g_z0 : (hop == 1) ? g_z1 : (hop == 2) ? g_z2 : g_h;
            float ax = 0.f, ay = 0.f, az = 0.f, aw = 0.f;
            if (active) {
                const float4* __restrict__ s4 = reinterpret_cast<const float4*>(sedge[r]);
                for (int s = p * 8; s < degp; s += 16) {
                    int q = s >> 1;
#pragma unroll
                    for (int t = 0; t < 4; t++) {
                        float4 e2 = s4[q + t];
                        float cj = half ? e2.z : e2.x;
                        float cc = half ? e2.w : e2.y;
                        float4 z = __ldg(reinterpret_cast<const float4*>(&zin[__float_as_int(cj) + h4]));
                        ax += cc * z.x; ay += cc * z.y; az += cc * z.z; aw += cc * z.w;
                    }
                }
                ax += __shfl_down_sync(0xffffffffu, ax, 16);
                ay += __shfl_down_sync(0xffffffffu, ay, 16);
                az += __shfl_down_sync(0xffffffffu, az, 16);
                aw += __shfl_down_sync(0xffffffffu, aw, 16);
            }
            if (half == 0) spart[w][hl] = make_float4(ax, ay, az, aw);
            __syncthreads();
            if (active && p == 0 && half == 0) {
                float4 pa = spart[w][hl];
                float4 pb = spart[w + 1][hl];
                float4 v4 = __ldg(reinterpret_cast<const float4*>(&gv[i * HID + h4]));
                float4 rr;
                rr.x = 0.85f * (pa.x + pb.x) + 0.15f * v4.x;
                rr.y = 0.85f * (pa.y + pb.y) + 0.15f * v4.y;
                rr.z = 0.85f * (pa.z + pb.z) + 0.15f * v4.z;
                rr.w = 0.85f * (pa.w + pb.w) + 0.15f * v4.w;
                if (hop == 3) {
                    int sb = r * (HID + 1) + h4;
                    rr.x += sh[sb + 0]; rr.y += sh[sb + 1];
                    rr.z += sh[sb + 2]; rr.w += sh[sb + 3];
                    sh[sb + 0] = rr.x; sh[sb + 1] = rr.y;
                    sh[sb + 2] = rr.z; sh[sb + 3] = rr.w;
                    if (l == 1)
                        *reinterpret_cast<float4*>(&g_h[i * HID + h4]) = rr;
                } else {
                    *reinterpret_cast<float4*>(&zout[i * HID + h4]) = rr;
                }
            }
            __syncthreads();
        }
    }

    // ---- cluster phase: logits + softmax + ss2 + P partials (own rows, smem h) ----
    for (int idx = tid; idx < HID * NGRP; idx += NTHREADS) sWg[idx] = Wg[idx];
    if (tid < NGRP) sbg2[tid] = bg[tid];
    __syncthreads();
    if (w < RPB && lane < 16) {
        int i2 = base + w;
        int sb = w * (HID + 1) + h4;
        float h0 = sh[sb + 0], h1 = sh[sb + 1], h2 = sh[sb + 2], h3 = sh[sb + 3];
        float lg0 = h0 * sWg[(h4+0)*4+0] + h1 * sWg[(h4+1)*4+0] + h2 * sWg[(h4+2)*4+0] + h3 * sWg[(h4+3)*4+0];
        float lg1 = h0 * sWg[(h4+0)*4+1] + h1 * sWg[(h4+1)*4+1] + h2 * sWg[(h4+2)*4+1] + h3 * sWg[(h4+3)*4+1];
        float lg2 = h0 * sWg[(h4+0)*4+2] + h1 * sWg[(h4+1)*4+2] + h2 * sWg[(h4+2)*4+2] + h3 * sWg[(h4+3)*4+2];
        float lg3 = h0 * sWg[(h4+0)*4+3] + h1 * sWg[(h4+1)*4+3] + h2 * sWg[(h4+2)*4+3] + h3 * sWg[(h4+3)*4+3];
#pragma unroll
        for (int o = 8; o > 0; o >>= 1) {
            lg0 += __shfl_xor_sync(0xffffu, lg0, o);
            lg1 += __shfl_xor_sync(0xffffu, lg1, o);
            lg2 += __shfl_xor_sync(0xffffu, lg2, o);
            lg3 += __shfl_xor_sync(0xffffu, lg3, o);
        }
        if (hl == 0) {
            if (i2 < N_NODES) {
                lg0 += sbg2[0]; lg1 += sbg2[1]; lg2 += sbg2[2]; lg3 += sbg2[3];
                float m = fmaxf(fmaxf(lg0, lg1), fmaxf(lg2, lg3));
                float e0 = __expf(lg0 - m), e1 = __expf(lg1 - m), e2 = __expf(lg2 - m), e3 = __expf(lg3 - m);
                float inv = 1.f / (e0 + e1 + e2 + e3);
                float s0 = e0 * inv, s1 = e1 * inv, s2 = e2 * inv, s3 = e3 * inv;
                g_ss2[i2] = s0 * s0 + s1 * s1 + s2 * s2 + s3 * s3;
                float wpv = __ldg(&Wp[i2]);
                sws[w][0] = s0 * wpv; sws[w][1] = s1 * wpv;
                sws[w][2] = s2 * wpv; sws[w][3] = s3 * wpv;
                sswp[w] = wpv;
            } else {
                sws[w][0] = sws[w][1] = sws[w][2] = sws[w][3] = 0.f;
                sswp[w] = 0.f;
            }
        }
    }
    __syncthreads();
    if (tid < 256) {
        int g = tid >> 6, h = tid & 63;
        float acc = 0.f;
#pragma unroll
        for (int rr = 0; rr < RPB; rr++)
            acc += sws[rr][g] * sh[rr * (HID + 1) + h];
        atomicAdd(&g_P[g * HID + h], acc);
    }
    if (tid < 32) {
        float v = (tid < RPB) ? sswp[tid] : 0.f;
#pragma unroll
        for (int o = 16; o > 0; o >>= 1) v += __shfl_xor_sync(0xffffffffu, v, o);
        if (tid == 0) atomicAdd(&g_P[NGRP * HID], v);
    }
    grid_barrier(8);   // P, ss2, h complete chip-wide

    // ---- finalize phase: 1 user per block, 128 threads (sequence split 2-way) ----
    int u = blockIdx.x;
    if (u < BATCH && tid < 128) {
        int grp = tid >> 6;
        int h = tid & 63;
        float S1 = 0.f, S2 = 0.f;
        for (int lq = grp; lq < SEQL; lq += 2) {
            int c = __ldg(&cate[u * SEQL + lq]);
            if (c != 0) {
                float gv2 = __ldg(&g_h[c * HID + h]);
                S1 += gv2;
                S2 += gv2 * gv2 * __ldg(&g_ss2[c]);
            }
        }
        sf1[tid] = S1;
        sf2[tid] = S2;
    }
    __syncthreads();
    if (u < BATCH && tid < 64) {
        int h = tid;
        float S1 = sf1[h] + sf1[h + 64];
        float S2 = sf2[h] + sf2[h + 64];
        const float invn = 1.f / (float)(NGRP * SEQL);
        float mean = S1 * invn;
        float var  = S2 * invn - mean * mean;
        float inv  = rsqrtf(var + 1e-5f);
        float ga = __ldg(&gamma[h]), be = __ldg(&beta[h]);
        float Swp = g_P[NGRP * HID];
        float bpv = __ldg(&bp[0]);
        float k1 = inv * ga;
        float addc = be * Swp + bpv;
        float ms = mean * Swp;
#pragma unroll
        for (int g = 0; g < NGRP; g++) {
            out[(u * NGRP + g) * HID + h] = k1 * (g_P[g * HID + h] - ms) + addc;
        }
    }
}

// ---------------- launch ----------------
extern "C" void kernel_launch(void* const* d_in, const int* in_sizes, int n_in,
                              void* d_out, int out_size)
{
    const int*   cate  = (const int*)  d_in[0];
    const float* adj   = (const float*)d_in[1];
    const float* emb   = (const float*)d_in[2];
    const float* Wq    = (const float*)d_in[3];
    const float* Wk    = (const float*)d_in[4];
    const float* Wv    = (const float*)d_in[5];
    const float* Wg    = (const float*)d_in[6];
    const float* bg    = (const float*)d_in[7];
    const float* Wp    = (const float*)d_in[8];
    const float* bp    = (const float*)d_in[9];
    const float* gamma = (const float*)d_in[10];
    const float* beta  = (const float*)d_in[11];
    float* out = (float*)d_out;

    static bool attr_set = false;
    if (!attr_set) {
        cudaFuncSetAttribute(mega_kernel,
                             cudaFuncAttributeMaxDynamicSharedMemorySize, MAGNA_SMEM);
        attr_set = true;
    }

    build_csr<<<N_NODES, 128>>>(adj);
    mega_kernel<<<GRID2, NTHREADS, MAGNA_SMEM>>>(
        emb, Wq, Wk, Wv, Wg, bg, Wp, bp, gamma, beta, cate, out);
}